// round 3
// baseline (speedup 1.0000x reference)
#include <cuda_runtime.h>
#include <cstdint>

// Forward 5/3 lifting wavelet, 2D separable, fused, register-heavy.
// x: (8, 32, 512, 512) f32 -> out: (8, 128, 256, 256) f32
// out channels: [LL(0:32) | LH(32:64) | HL(64:96) | HH(96:128)]
//
//   d[i] = x[2i+1] - 0.5*(even[refl(i-1)] + even[refl(i+1)])
//   s[i] = x[2i]   + 0.25*(d[refl(i-1)] + d[refl(i+1)])
// refl: -1 -> 1, 256 -> 254

static constexpr int H = 512;
static constexpr int Wd = 512;
static constexpr int R = 32;              // output rows per strip
static constexpr int NSTRIP = 256 / R;    // 8
static constexpr int NBC = 8 * 32;        // 256 images
static constexpr int MAXROWS = 2 * R + 7; // 71
static constexpr int SMEM_BYTES = MAXROWS * Wd * 4; // 145408

__device__ __forceinline__ int REFL(int i) {
    return (i < 0) ? -i : ((i > 255) ? 510 - i : i);
}

__global__ __launch_bounds__(1024, 1)
void lwt53_fused_kernel(const float* __restrict__ x, float* __restrict__ out) {
    extern __shared__ float A[];   // [nrows][512]; per row: s in [0,256), d in [256,512)

    const unsigned FULL = 0xffffffffu;
    const int blk   = blockIdx.x;
    const int strip = blk & (NSTRIP - 1);
    const int bc    = blk >> 3;            // log2(NSTRIP)=3
    const int r0    = strip * R;

    const int mlo   = max(0, 2 * r0 - 4);
    const int mhi   = min(H - 1, 2 * r0 + 2 * R + 2);
    const int nrows = mhi - mlo + 1;

    const float* __restrict__ xim = x + (size_t)bc * (H * Wd) + (size_t)mlo * Wd;

    const int tid  = threadIdx.x;
    const int warp = tid >> 5;
    const int lane = tid & 31;

    // ================= Phase A: row lifting in registers =================
    // Warp handles whole rows. Lane l owns pairs (64j+2l, 64j+2l+1), j=0..3 —
    // exactly one coalesced float4 load.
    for (int r = warp; r < nrows; r += 32) {
        const float4* __restrict__ xr =
            reinterpret_cast<const float4*>(xim + (size_t)r * Wd);
        float eA[4], oA[4], eB[4], oB[4];
        #pragma unroll
        for (int j = 0; j < 4; j++) {
            const float4 v = xr[32 * j + lane];
            eA[j] = v.x; oA[j] = v.y; eB[j] = v.z; oB[j] = v.w;
        }

        float dA[4], dB[4];
        #pragma unroll
        for (int j = 0; j < 4; j++) {
            float up = __shfl_up_sync(FULL, eB[j], 1);
            float cp = __shfl_sync(FULL, (j > 0) ? eB[j - 1] : eB[j], 31);
            float Eprev = (lane == 0) ? ((j == 0) ? eB[0] : cp) : up;   // refl i=0
            float dn = __shfl_down_sync(FULL, eA[j], 1);
            float cn = __shfl_sync(FULL, (j < 3) ? eA[j + 1] : eA[j], 0);
            float Enext = (lane == 31) ? ((j == 3) ? eA[3] : cn) : dn;  // refl i=255
            dA[j] = oA[j] - 0.5f * (Eprev + eB[j]);
            dB[j] = oB[j] - 0.5f * (eA[j] + Enext);
        }

        float* Arow = A + r * Wd;
        float2* __restrict__ srow = reinterpret_cast<float2*>(Arow);
        float2* __restrict__ drow = reinterpret_cast<float2*>(Arow + 256);
        #pragma unroll
        for (int j = 0; j < 4; j++) {
            float up = __shfl_up_sync(FULL, dB[j], 1);
            float cp = __shfl_sync(FULL, (j > 0) ? dB[j - 1] : dB[j], 31);
            float Dprev = (lane == 0) ? ((j == 0) ? dB[0] : cp) : up;
            float dn = __shfl_down_sync(FULL, dA[j], 1);
            float cn = __shfl_sync(FULL, (j < 3) ? dA[j + 1] : dA[j], 0);
            float Dnext = (lane == 31) ? ((j == 3) ? dA[3] : cn) : dn;
            float sA = eA[j] + 0.25f * (Dprev + dB[j]);
            float sB = eB[j] + 0.25f * (dA[j] + Dnext);
            srow[32 * j + lane] = make_float2(sA, sB);
            drow[32 * j + lane] = make_float2(dA[j], dB[j]);
        }
    }
    __syncthreads();

    // ================= Phase B: column lifting in registers =================
    // Thread owns smem column t (t<256: s-cols -> LL/LH; else d-cols -> HL/HH),
    // and one 16-row half of the strip. All register-array indices are
    // compile-time constants; boundary reflection via value copies.
    {
        const int t    = tid & 511;
        const int half = tid >> 9;
        const int r0h  = r0 + 16 * half;   // first output row of this thread
        const int j0e  = r0h - 2;          // even-cache base index

        // e[q] = column-sample at even position REFL(j0e+q)
        float e[20];
        #pragma unroll
        for (int q = 0; q < 20; q++) {
            const int idx = REFL(j0e + q);
            e[q] = A[(2 * idx - mlo) * Wd + t];
        }

        // d[q] = d at position refl(r0h-1+q); interior formula uses e[q],e[q+2]
        float d[18];
        #pragma unroll
        for (int q = 0; q < 18; q++) {
            const int j = REFL(r0h - 1 + q);
            const float odd = A[(2 * j + 1 - mlo) * Wd + t];
            d[q] = odd - 0.5f * (e[q] + e[q + 2]);
        }
        // boundary fixups: d at reflected index equals its mirror
        if (r0h == 0)   d[0]  = d[2];    // j=-1 -> 1
        if (r0h == 240) d[17] = d[15];   // j=256 -> 254

        const int b = bc >> 5;
        const int c = bc & 31;
        const size_t band = (size_t)256 * 256;
        float* __restrict__ base = out + ((size_t)b * 128 + c) * band;
        float* __restrict__ sOut = base + ((t < 256) ? (size_t)0 : 64 * band);
        float* __restrict__ dOut = base + ((t < 256) ? 32 * band : 96 * band);
        const int col = t & 255;

        #pragma unroll
        for (int q = 0; q < 16; q++) {
            const int k = r0h + q;
            const float s = e[q + 2] + 0.25f * (d[q] + d[q + 2]);
            const size_t o = (size_t)k * 256 + col;
            __stcs(sOut + o, s);
            __stcs(dOut + o, d[q + 1]);
        }
    }
}

extern "C" void kernel_launch(void* const* d_in, const int* in_sizes, int n_in,
                              void* d_out, int out_size) {
    const float* x = (const float*)d_in[0];
    float* out = (float*)d_out;
    (void)in_sizes; (void)n_in; (void)out_size;

    static bool attr_set = false;
    if (!attr_set) {
        cudaFuncSetAttribute(lwt53_fused_kernel,
                             cudaFuncAttributeMaxDynamicSharedMemorySize, SMEM_BYTES);
        attr_set = true;
    }

    dim3 grid(NBC * NSTRIP);   // 2048
    dim3 block(1024);
    lwt53_fused_kernel<<<grid, block, SMEM_BYTES>>>(x, out);
}

// round 4
// speedup vs baseline: 1.1027x; 1.1027x over previous
#include <cuda_runtime.h>
#include <cstdint>

// Forward 5/3 lifting wavelet, 2D separable, fused, register-heavy.
// x: (8, 32, 512, 512) f32 -> out: (8, 128, 256, 256) f32
// out channels: [LL(0:32) | LH(32:64) | HL(64:96) | HH(96:128)]
//
//   d[i] = x[2i+1] - 0.5*(even[refl(i-1)] + even[refl(i+1)])
//   s[i] = x[2i]   + 0.25*(d[refl(i-1)] + d[refl(i+1)])
// refl: -1 -> 1, 256 -> 254

static constexpr int H = 512;
static constexpr int Wd = 512;
static constexpr int R = 16;              // output rows per strip
static constexpr int NSTRIP = 256 / R;    // 16
static constexpr int NBC = 8 * 32;        // 256 images
static constexpr int MAXROWS = 2 * R + 7; // 39
static constexpr int SMEM_BYTES = MAXROWS * Wd * 4; // 79872

__device__ __forceinline__ int REFL(int i) {
    return (i < 0) ? -i : ((i > 255) ? 510 - i : i);
}

__global__ __launch_bounds__(512, 2)
void lwt53_fused_kernel(const float* __restrict__ x, float* __restrict__ out) {
    extern __shared__ float A[];   // [nrows][512]; per row: s in [0,256), d in [256,512)

    const unsigned FULL = 0xffffffffu;
    const int blk   = blockIdx.x;
    const int strip = blk & (NSTRIP - 1);
    const int bc    = blk >> 4;            // log2(NSTRIP)=4
    const int r0    = strip * R;

    const int mlo   = max(0, 2 * r0 - 4);
    const int mhi   = min(H - 1, 2 * r0 + 2 * R + 2);
    const int nrows = mhi - mlo + 1;

    const float* __restrict__ xim = x + (size_t)bc * (H * Wd) + (size_t)mlo * Wd;

    const int tid  = threadIdx.x;
    const int warp = tid >> 5;
    const int lane = tid & 31;

    // ================= Phase A: row lifting in registers =================
    // Warp handles whole rows. Lane l owns pairs (64j+2l, 64j+2l+1), j=0..3 —
    // exactly one coalesced float4 load.
    for (int r = warp; r < nrows; r += 16) {
        const float4* __restrict__ xr =
            reinterpret_cast<const float4*>(xim + (size_t)r * Wd);
        float eA[4], oA[4], eB[4], oB[4];
        #pragma unroll
        for (int j = 0; j < 4; j++) {
            const float4 v = xr[32 * j + lane];
            eA[j] = v.x; oA[j] = v.y; eB[j] = v.z; oB[j] = v.w;
        }

        float dA[4], dB[4];
        #pragma unroll
        for (int j = 0; j < 4; j++) {
            float up = __shfl_up_sync(FULL, eB[j], 1);
            float cp = __shfl_sync(FULL, (j > 0) ? eB[j - 1] : eB[j], 31);
            float Eprev = (lane == 0) ? ((j == 0) ? eB[0] : cp) : up;   // refl i=0
            float dn = __shfl_down_sync(FULL, eA[j], 1);
            float cn = __shfl_sync(FULL, (j < 3) ? eA[j + 1] : eA[j], 0);
            float Enext = (lane == 31) ? ((j == 3) ? eA[3] : cn) : dn;  // refl i=255
            dA[j] = oA[j] - 0.5f * (Eprev + eB[j]);
            dB[j] = oB[j] - 0.5f * (eA[j] + Enext);
        }

        float* Arow = A + r * Wd;
        float2* __restrict__ srow = reinterpret_cast<float2*>(Arow);
        float2* __restrict__ drow = reinterpret_cast<float2*>(Arow + 256);
        #pragma unroll
        for (int j = 0; j < 4; j++) {
            float up = __shfl_up_sync(FULL, dB[j], 1);
            float cp = __shfl_sync(FULL, (j > 0) ? dB[j - 1] : dB[j], 31);
            float Dprev = (lane == 0) ? ((j == 0) ? dB[0] : cp) : up;
            float dn = __shfl_down_sync(FULL, dA[j], 1);
            float cn = __shfl_sync(FULL, (j < 3) ? dA[j + 1] : dA[j], 0);
            float Dnext = (lane == 31) ? ((j == 3) ? dA[3] : cn) : dn;
            float sA = eA[j] + 0.25f * (Dprev + dB[j]);
            float sB = eB[j] + 0.25f * (dA[j] + Dnext);
            srow[32 * j + lane] = make_float2(sA, sB);
            drow[32 * j + lane] = make_float2(dA[j], dB[j]);
        }
    }
    __syncthreads();

    // ================= Phase B: column lifting in registers =================
    // Thread owns smem column t (t<256: s-cols -> LL/LH; else d-cols -> HL/HH),
    // covering all 16 output rows of the strip. Even rows cached in registers
    // (loaded once, reused by predict and update). All register-array indices
    // are compile-time constants; boundary reflection via value copies.
    {
        const int t   = tid;
        const int j0e = r0 - 2;

        // e[q] = column-sample at even position REFL(j0e+q), q=0..19
        float e[20];
        #pragma unroll
        for (int q = 0; q < 20; q++) {
            const int idx = REFL(j0e + q);
            e[q] = A[(2 * idx - mlo) * Wd + t];
        }

        // d[q] = d at position refl(r0-1+q), q=0..17
        float d[18];
        #pragma unroll
        for (int q = 0; q < 18; q++) {
            const int j = REFL(r0 - 1 + q);
            const float odd = A[(2 * j + 1 - mlo) * Wd + t];
            d[q] = odd - 0.5f * (e[q] + e[q + 2]);
        }
        // boundary fixups: reflected d equals its mirror
        if (r0 == 0)   d[0]  = d[2];    // j=-1 -> 1
        if (r0 == 240) d[17] = d[15];   // j=256 -> 254

        const int b = bc >> 5;
        const int c = bc & 31;
        const size_t band = (size_t)256 * 256;
        float* __restrict__ base = out + ((size_t)b * 128 + c) * band;
        float* __restrict__ sOut = base + ((t < 256) ? (size_t)0 : 64 * band);
        float* __restrict__ dOut = base + ((t < 256) ? 32 * band : 96 * band);
        const int col = t & 255;

        #pragma unroll
        for (int q = 0; q < 16; q++) {
            const int k = r0 + q;
            const float s = e[q + 2] + 0.25f * (d[q] + d[q + 2]);
            const size_t o = (size_t)k * 256 + col;
            __stcs(sOut + o, s);
            __stcs(dOut + o, d[q + 1]);
        }
    }
}

extern "C" void kernel_launch(void* const* d_in, const int* in_sizes, int n_in,
                              void* d_out, int out_size) {
    const float* x = (const float*)d_in[0];
    float* out = (float*)d_out;
    (void)in_sizes; (void)n_in; (void)out_size;

    static bool attr_set = false;
    if (!attr_set) {
        cudaFuncSetAttribute(lwt53_fused_kernel,
                             cudaFuncAttributeMaxDynamicSharedMemorySize, SMEM_BYTES);
        attr_set = true;
    }

    dim3 grid(NBC * NSTRIP);   // 4096
    dim3 block(512);
    lwt53_fused_kernel<<<grid, block, SMEM_BYTES>>>(x, out);
}